// round 1
// baseline (speedup 1.0000x reference)
#include <cuda_runtime.h>
#include <math.h>

// Problem constants
//  B=64, N=236, C=768, H=8, D=96, 3C=2304
//  M = B*N = 15104 (= 118*128 exactly)
#define BM 128
#define BN 128
#define BK 8

// Scratch (static device globals -- no runtime allocation allowed)
__device__ float g_qkv[15104 * 2304];      // [B*N, 3C] : q|k|v interleaved per row (t*768 + h*96 + d)
__device__ float g_S[512 * 236 * 236];     // [B*H, 236, 236] attention logits -> probabilities
__device__ float g_att[15104 * 768];       // [B, N, C] attention output (h*96+d contiguous)

// ---------------------------------------------------------------------------
// Generic batched SGEMM:
//   TRANS_B = true :  C[m,n] = alpha * sum_k A[m,k] * B[n,k]   (both row-major, K contiguous)
//   TRANS_B = false:  C[m,n] = alpha * sum_k A[m,k] * B[k,n]   (B row-major [K,N])
// Batch index z = bb*HB + hb; per-matrix offsets = bb*s?b + hb*s?h  (handles the
// non-affine (b,h) -> offset maps into the packed qkv buffer).
// 128x128x8 tile, 256 threads, 8x8 per-thread register tile, double-buffered smem.
// ---------------------------------------------------------------------------
template<bool TRANS_B, bool ADD_BIAS>
__global__ void __launch_bounds__(256, 2)
gemm_kernel(const float* __restrict__ Ag, const float* __restrict__ Bg,
            const float* __restrict__ bias, float* __restrict__ Cg,
            int M, int N, int K, int lda, int ldb, int ldc,
            int HB, long sAb, long sAh, long sBb, long sBh, long sCb, long sCh,
            float alpha)
{
    const int z  = blockIdx.z;
    const int hb = z % HB;
    const int bb = z / HB;
    const float* A = Ag + bb * sAb + hb * sAh;
    const float* B = Bg + bb * sBb + hb * sBh;
    float*       C = Cg + bb * sCb + hb * sCh;

    const int bm = blockIdx.x * BM;
    const int bn = blockIdx.y * BN;

    __shared__ float As[2][BK][BM];
    __shared__ float Bs[2][BK][BN];

    const int tid = threadIdx.x;
    const int tx  = tid & 15;   // column group (8 cols each)
    const int ty  = tid >> 4;   // row group (8 rows each)

    float acc[8][8];
#pragma unroll
    for (int i = 0; i < 8; i++)
#pragma unroll
        for (int j = 0; j < 8; j++) acc[i][j] = 0.0f;

    // global-load thread mappings
    const int am = tid >> 1;            // A: row within tile (0..127)
    const int ak = (tid & 1) * 4;       // A: k offset (0 or 4)
    const int btr_n = tid >> 1;         // B (NT): n within tile
    const int btr_k = (tid & 1) * 4;    // B (NT): k offset
    const int bnn_k = tid >> 5;         // B (NN): k within tile (0..7)
    const int bnn_n = (tid & 31) * 4;   // B (NN): n offset (0..124)

    const int ntiles = (K + BK - 1) / BK;

    float ra[4], rb[4];

    auto loadA = [&](int k0) {
        int row = bm + am;
        int col = k0 + ak;
        if (row < M && col + 3 < K) {
            float4 v = *reinterpret_cast<const float4*>(A + (long)row * lda + col);
            ra[0] = v.x; ra[1] = v.y; ra[2] = v.z; ra[3] = v.w;
        } else {
#pragma unroll
            for (int i = 0; i < 4; i++)
                ra[i] = (row < M && col + i < K) ? A[(long)row * lda + col + i] : 0.0f;
        }
    };
    auto loadB = [&](int k0) {
        if (TRANS_B) {
            int row = bn + btr_n;
            int col = k0 + btr_k;
            if (row < N && col + 3 < K) {
                float4 v = *reinterpret_cast<const float4*>(B + (long)row * ldb + col);
                rb[0] = v.x; rb[1] = v.y; rb[2] = v.z; rb[3] = v.w;
            } else {
#pragma unroll
                for (int i = 0; i < 4; i++)
                    rb[i] = (row < N && col + i < K) ? B[(long)row * ldb + col + i] : 0.0f;
            }
        } else {
            int kk = k0 + bnn_k;
            int cc = bn + bnn_n;
            if (kk < K && cc + 3 < N) {
                float4 v = *reinterpret_cast<const float4*>(B + (long)kk * ldb + cc);
                rb[0] = v.x; rb[1] = v.y; rb[2] = v.z; rb[3] = v.w;
            } else {
#pragma unroll
                for (int i = 0; i < 4; i++)
                    rb[i] = (kk < K && cc + i < N) ? B[(long)kk * ldb + cc + i] : 0.0f;
            }
        }
    };
    auto storeAB = [&](int buf) {
#pragma unroll
        for (int i = 0; i < 4; i++) As[buf][ak + i][am] = ra[i];
        if (TRANS_B) {
#pragma unroll
            for (int i = 0; i < 4; i++) Bs[buf][btr_k + i][btr_n] = rb[i];
        } else {
            float4 v; v.x = rb[0]; v.y = rb[1]; v.z = rb[2]; v.w = rb[3];
            *reinterpret_cast<float4*>(&Bs[buf][bnn_k][bnn_n]) = v;
        }
    };

    loadA(0); loadB(0);
    storeAB(0);
    __syncthreads();

    for (int t = 0; t < ntiles; ++t) {
        const int cur = t & 1;
        if (t + 1 < ntiles) { loadA((t + 1) * BK); loadB((t + 1) * BK); }

#pragma unroll
        for (int kk = 0; kk < BK; ++kk) {
            float a[8], b[8];
            *reinterpret_cast<float4*>(&a[0]) = *reinterpret_cast<const float4*>(&As[cur][kk][ty * 8]);
            *reinterpret_cast<float4*>(&a[4]) = *reinterpret_cast<const float4*>(&As[cur][kk][ty * 8 + 4]);
            *reinterpret_cast<float4*>(&b[0]) = *reinterpret_cast<const float4*>(&Bs[cur][kk][tx * 8]);
            *reinterpret_cast<float4*>(&b[4]) = *reinterpret_cast<const float4*>(&Bs[cur][kk][tx * 8 + 4]);
#pragma unroll
            for (int i = 0; i < 8; i++)
#pragma unroll
                for (int j = 0; j < 8; j++)
                    acc[i][j] = fmaf(a[i], b[j], acc[i][j]);
        }

        if (t + 1 < ntiles) {
            storeAB(cur ^ 1);   // safe: buffer cur^1 was last read before previous sync
            __syncthreads();
        }
    }

    // epilogue
#pragma unroll
    for (int i = 0; i < 8; i++) {
        int r = bm + ty * 8 + i;
        if (r >= M) continue;
        float* crow = C + (long)r * ldc;
#pragma unroll
        for (int j0 = 0; j0 < 8; j0 += 4) {
            int c = bn + tx * 8 + j0;
            if (c + 3 < N) {
                float4 v;
                v.x = acc[i][j0 + 0] * alpha;
                v.y = acc[i][j0 + 1] * alpha;
                v.z = acc[i][j0 + 2] * alpha;
                v.w = acc[i][j0 + 3] * alpha;
                if (ADD_BIAS) {
                    v.x += bias[c + 0]; v.y += bias[c + 1];
                    v.z += bias[c + 2]; v.w += bias[c + 3];
                }
                *reinterpret_cast<float4*>(crow + c) = v;
            } else {
#pragma unroll
                for (int u = 0; u < 4; u++) {
                    int cc = c + u;
                    if (cc < N)
                        crow[cc] = acc[i][j0 + u] * alpha + (ADD_BIAS ? bias[cc] : 0.0f);
                }
            }
        }
    }
}

// ---------------------------------------------------------------------------
// Block edits + softmax, one CTA (256 threads) per attention row.
//   rows < 196:   col[216:236] := pre-bias col[196:216];  col[196:216] -= 100
//   rows 196:216: col[216:236] -= 100
//   rows 216:236: col[196:216] -= 100
// then softmax over 236 columns (in place: logits -> probabilities).
// ---------------------------------------------------------------------------
__global__ void softmax_edit_kernel(float* __restrict__ S)
{
    const int r  = blockIdx.x;   // 0..235
    const int bh = blockIdx.y;   // 0..511
    float* srow = S + ((long)bh * 236 + r) * 236;
    const int c = threadIdx.x;

    float v = -1e30f;
    if (c < 236) {
        float s;
        if (r < 196) {
            if (c >= 216)      s = srow[c - 20];          // copy uses PRE-bias values
            else if (c >= 196) s = srow[c] - 100.0f;
            else               s = srow[c];
        } else if (r < 216) {
            s = srow[c] - ((c >= 216) ? 100.0f : 0.0f);
        } else {
            s = srow[c] - ((c >= 196 && c < 216) ? 100.0f : 0.0f);
        }
        v = s;
    }

    __shared__ float red[8];
    // max reduce
    float m = v;
#pragma unroll
    for (int o = 16; o > 0; o >>= 1) m = fmaxf(m, __shfl_xor_sync(0xffffffffu, m, o));
    if ((c & 31) == 0) red[c >> 5] = m;
    __syncthreads();
    float mx = fmaxf(fmaxf(fmaxf(red[0], red[1]), fmaxf(red[2], red[3])),
                     fmaxf(fmaxf(red[4], red[5]), fmaxf(red[6], red[7])));

    float e = (c < 236) ? expf(v - mx) : 0.0f;
    // sum reduce
    float ssum = e;
#pragma unroll
    for (int o = 16; o > 0; o >>= 1) ssum += __shfl_xor_sync(0xffffffffu, ssum, o);
    __syncthreads();                 // everyone done reading red[] for max
    if ((c & 31) == 0) red[c >> 5] = ssum;
    __syncthreads();
    float tot = red[0] + red[1] + red[2] + red[3] + red[4] + red[5] + red[6] + red[7];

    if (c < 236) srow[c] = e / tot;
}

// ---------------------------------------------------------------------------
extern "C" void kernel_launch(void* const* d_in, const int* in_sizes, int n_in,
                              void* d_out, int out_size)
{
    const float* x      = (const float*)d_in[0];   // [64,236,768]
    const float* qkv_w  = (const float*)d_in[1];   // [2304,768]
    const float* proj_w = (const float*)d_in[2];   // [768,768]
    const float* proj_b = (const float*)d_in[3];   // [768]
    float* out = (float*)d_out;                    // [64,236,768]

    float *qkv, *S, *att;
    cudaGetSymbolAddress((void**)&qkv, g_qkv);
    cudaGetSymbolAddress((void**)&S,   g_S);
    cudaGetSymbolAddress((void**)&att, g_att);

    dim3 thr(256);

    // 1) qkv = x @ qkv_w^T        [15104 x 2304], K=768
    gemm_kernel<true, false><<<dim3(118, 18, 1), thr>>>(
        x, qkv_w, nullptr, qkv,
        15104, 2304, 768, 768, 768, 2304,
        1, 0, 0, 0, 0, 0, 0, 1.0f);

    // 2) S[b,h] = Q @ K^T * scale   (512 batches, 236x236x96)
    //    Q row stride 2304; offsets: b*236*2304 + h*96 (+768 for K)
    const float scale = 0.10206207261596575f;   // 1/sqrt(96)
    gemm_kernel<true, false><<<dim3(2, 2, 512), thr>>>(
        qkv, qkv + 768, nullptr, S,
        236, 236, 96, 2304, 2304, 236,
        8, (long)236 * 2304, 96, (long)236 * 2304, 96,
        (long)8 * 236 * 236, (long)236 * 236,
        scale);

    // 3) block edits + softmax (in place on S)
    softmax_edit_kernel<<<dim3(236, 512), thr>>>(S);

    // 4) att[b, s, h*96+d] = P @ V   (512 batches, 236x96x236)
    gemm_kernel<false, false><<<dim3(2, 1, 512), thr>>>(
        S, qkv + 1536, nullptr, att,
        236, 96, 236, 236, 2304, 768,
        8, (long)8 * 236 * 236, (long)236 * 236,
        (long)236 * 2304, 96,
        (long)236 * 768, 96,
        1.0f);

    // 5) out = att @ proj_w^T + proj_b   [15104 x 768], K=768
    gemm_kernel<true, true><<<dim3(118, 6, 1), thr>>>(
        att, proj_w, proj_b, out,
        15104, 768, 768, 768, 768, 768,
        1, 0, 0, 0, 0, 0, 0, 1.0f);
}

// round 5
// speedup vs baseline: 1.5686x; 1.5686x over previous
#include <cuda_runtime.h>
#include <cstdint>
#include <math.h>

// ---------------------------------------------------------------------------
// Problem: B=64, N=236, C=768, H=8, D=96.  M = B*N = 15104 = 118*128.
// Scratch (static device globals -- no runtime allocation allowed)
// ---------------------------------------------------------------------------
__device__ float g_qkv[(size_t)15104 * 2304];   // [B*N, 3C]
__device__ float g_S[(size_t)512 * 236 * 236];  // [B*H, 236, 236]
__device__ float g_att[(size_t)15104 * 768];    // [B, N, C]
__device__ float g_vt[(size_t)512 * 96 * 236];  // [B*H, 96, 236] (V transposed)

// ---------------------------------------------------------------------------
__device__ __forceinline__ float to_tf32(float x) {
    uint32_t r;
    asm("cvt.rna.tf32.f32 %0, %1;" : "=r"(r) : "f"(x));
    return __uint_as_float(r);
}

__device__ __forceinline__ void mma_tf32(float* c, const uint32_t* a, const uint32_t* b) {
    asm volatile(
        "mma.sync.aligned.m16n8k8.row.col.f32.tf32.tf32.f32 "
        "{%0,%1,%2,%3}, {%4,%5,%6,%7}, {%8,%9}, {%0,%1,%2,%3};"
        : "+f"(c[0]), "+f"(c[1]), "+f"(c[2]), "+f"(c[3])
        : "r"(a[0]), "r"(a[1]), "r"(a[2]), "r"(a[3]), "r"(b[0]), "r"(b[1]));
}

// ---------------------------------------------------------------------------
// tf32 tensor-core batched NT GEMM: C[m,n] = alpha*sum_k A[m,k]*B[n,k] (+bias[n])
// 128x128x16 tile, 256 threads (8 warps, 4x2), warp tile 32x64, double-buffered.
// ---------------------------------------------------------------------------
template<bool ADD_BIAS>
__global__ void __launch_bounds__(256, 2)
mma_gemm(const float* __restrict__ Ag, const float* __restrict__ Bg,
         const float* __restrict__ bias, float* __restrict__ Cg,
         int M, int N, int K, int lda, int ldb, int ldc,
         int HB, long sAb, long sAh, long sBb, long sBh, long sCb, long sCh,
         float alpha)
{
    __shared__ float As[2][16][132];
    __shared__ float Bs[2][16][132];

    const int z  = blockIdx.z;
    const int hb = z % HB, bb = z / HB;
    const float* A = Ag + (size_t)bb * sAb + (size_t)hb * sAh;
    const float* B = Bg + (size_t)bb * sBb + (size_t)hb * sBh;
    float*       C = Cg + (size_t)bb * sCb + (size_t)hb * sCh;

    const int bm = blockIdx.x * 128, bn = blockIdx.y * 128;
    const int tid = threadIdx.x, lane = tid & 31, wid = tid >> 5;
    const int wr = wid & 3, wc = wid >> 2;          // warp row (x32), warp col (x64)
    const int r0 = tid & 127;                       // load row within tile

    float acc[2][8][4];
#pragma unroll
    for (int t2 = 0; t2 < 2; t2++)
#pragma unroll
        for (int j = 0; j < 8; j++)
#pragma unroll
            for (int u = 0; u < 4; u++) acc[t2][j][u] = 0.0f;

    float4 ra[2], rb[2];

    auto loadTile = [&](int k0) {
#pragma unroll
        for (int i = 0; i < 2; i++) {
            int c4 = (tid + i * 256) >> 7;          // 0..3 -> k offset c4*4
            int gc = k0 + c4 * 4;
            int gr = bm + r0;
            float4 v = make_float4(0.f, 0.f, 0.f, 0.f);
            if (gr < M && gc < K) v = *reinterpret_cast<const float4*>(A + (size_t)gr * lda + gc);
            ra[i] = v;
            gr = bn + r0;
            v = make_float4(0.f, 0.f, 0.f, 0.f);
            if (gr < N && gc < K) v = *reinterpret_cast<const float4*>(B + (size_t)gr * ldb + gc);
            rb[i] = v;
        }
    };
    auto storeTile = [&](int buf) {
#pragma unroll
        for (int i = 0; i < 2; i++) {
            int c4 = (tid + i * 256) >> 7;
            As[buf][c4 * 4 + 0][r0] = to_tf32(ra[i].x);
            As[buf][c4 * 4 + 1][r0] = to_tf32(ra[i].y);
            As[buf][c4 * 4 + 2][r0] = to_tf32(ra[i].z);
            As[buf][c4 * 4 + 3][r0] = to_tf32(ra[i].w);
            Bs[buf][c4 * 4 + 0][r0] = to_tf32(rb[i].x);
            Bs[buf][c4 * 4 + 1][r0] = to_tf32(rb[i].y);
            Bs[buf][c4 * 4 + 2][r0] = to_tf32(rb[i].z);
            Bs[buf][c4 * 4 + 3][r0] = to_tf32(rb[i].w);
        }
    };
    auto compute = [&](int buf) {
        const int q = lane >> 2, r = lane & 3;
#pragma unroll
        for (int ks = 0; ks < 16; ks += 8) {
            uint32_t a[2][4], b[8][2];
#pragma unroll
            for (int t2 = 0; t2 < 2; t2++) {
                int m0 = wr * 32 + t2 * 16 + q;
                a[t2][0] = __float_as_uint(As[buf][ks + r][m0]);
                a[t2][1] = __float_as_uint(As[buf][ks + r][m0 + 8]);
                a[t2][2] = __float_as_uint(As[buf][ks + r + 4][m0]);
                a[t2][3] = __float_as_uint(As[buf][ks + r + 4][m0 + 8]);
            }
#pragma unroll
            for (int j = 0; j < 8; j++) {
                int n0 = wc * 64 + j * 8 + q;
                b[j][0] = __float_as_uint(Bs[buf][ks + r][n0]);
                b[j][1] = __float_as_uint(Bs[buf][ks + r + 4][n0]);
            }
#pragma unroll
            for (int t2 = 0; t2 < 2; t2++)
#pragma unroll
                for (int j = 0; j < 8; j++)
                    mma_tf32(acc[t2][j], a[t2], b[j]);
        }
    };

    const int ntiles = (K + 15) / 16;
    loadTile(0);
    storeTile(0);
    __syncthreads();

    for (int t = 0; t < ntiles; t++) {
        const int cur = t & 1;
        if (t + 1 < ntiles) loadTile((t + 1) * 16);
        compute(cur);
        if (t + 1 < ntiles) { storeTile(cur ^ 1); __syncthreads(); }
    }

    // epilogue (c0,c1 -> row, c2,c3 -> row+8; cols col, col+1)
#pragma unroll
    for (int t2 = 0; t2 < 2; t2++) {
#pragma unroll
        for (int j = 0; j < 8; j++) {
            int col = bn + wc * 64 + j * 8 + (lane & 3) * 2;
            if (col >= N) continue;
            int row0 = bm + wr * 32 + t2 * 16 + (lane >> 2);
            float bx = 0.f, by = 0.f;
            if (ADD_BIAS) { bx = bias[col]; by = bias[col + 1]; }
            if (row0 < M) {
                float2 v;
                v.x = acc[t2][j][0] * alpha + bx;
                v.y = acc[t2][j][1] * alpha + by;
                *reinterpret_cast<float2*>(C + (size_t)row0 * ldc + col) = v;
            }
            if (row0 + 8 < M) {
                float2 v;
                v.x = acc[t2][j][2] * alpha + bx;
                v.y = acc[t2][j][3] * alpha + by;
                *reinterpret_cast<float2*>(C + (size_t)(row0 + 8) * ldc + col) = v;
            }
        }
    }
}

// ---------------------------------------------------------------------------
// V transpose: vt[bh][d][t] = qkv[(b*236+t)*2304 + 1536 + h*96 + d]
// ---------------------------------------------------------------------------
__global__ void vtrans_kernel(const float* __restrict__ qkv, float* __restrict__ vt)
{
    __shared__ float t[32][33];
    const int bh = blockIdx.z;
    const int b = bh >> 3, h = bh & 7;
    const int t0 = blockIdx.x * 32;
    const int d0 = blockIdx.y * 32;
    const int tx = threadIdx.x, ty = threadIdx.y;

#pragma unroll
    for (int r = ty; r < 32; r += 8) {
        int tok = t0 + r;
        int d = d0 + tx;
        float v = 0.f;
        if (tok < 236)
            v = qkv[(size_t)(b * 236 + tok) * 2304 + 1536 + h * 96 + d];
        t[r][tx] = v;
    }
    __syncthreads();
#pragma unroll
    for (int r = ty; r < 32; r += 8) {
        int d = d0 + r;
        int tok = t0 + tx;
        if (tok < 236)
            vt[((size_t)bh * 96 + d) * 236 + tok] = t[tx][r];
    }
}

// ---------------------------------------------------------------------------
// Block edits + softmax (one 256-thread CTA per attention row)
// ---------------------------------------------------------------------------
__global__ void softmax_edit_kernel(float* __restrict__ S)
{
    const int r  = blockIdx.x;   // 0..235
    const int bh = blockIdx.y;   // 0..511
    float* srow = S + ((size_t)bh * 236 + r) * 236;
    const int c = threadIdx.x;

    float v = -1e30f;
    if (c < 236) {
        float s;
        if (r < 196) {
            if (c >= 216)      s = srow[c - 20];      // copy uses PRE-bias values
            else if (c >= 196) s = srow[c] - 100.0f;
            else               s = srow[c];
        } else if (r < 216) {
            s = srow[c] - ((c >= 216) ? 100.0f : 0.0f);
        } else {
            s = srow[c] - ((c >= 196 && c < 216) ? 100.0f : 0.0f);
        }
        v = s;
    }

    __shared__ float red[8];
    float m = v;
#pragma unroll
    for (int o = 16; o > 0; o >>= 1) m = fmaxf(m, __shfl_xor_sync(0xffffffffu, m, o));
    if ((c & 31) == 0) red[c >> 5] = m;
    __syncthreads();
    float mx = fmaxf(fmaxf(fmaxf(red[0], red[1]), fmaxf(red[2], red[3])),
                     fmaxf(fmaxf(red[4], red[5]), fmaxf(red[6], red[7])));

    float e = (c < 236) ? expf(v - mx) : 0.0f;
    float ssum = e;
#pragma unroll
    for (int o = 16; o > 0; o >>= 1) ssum += __shfl_xor_sync(0xffffffffu, ssum, o);
    __syncthreads();
    if ((c & 31) == 0) red[c >> 5] = ssum;
    __syncthreads();
    float tot = red[0] + red[1] + red[2] + red[3] + red[4] + red[5] + red[6] + red[7];

    if (c < 236) srow[c] = e / tot;
}

// ---------------------------------------------------------------------------
extern "C" void kernel_launch(void* const* d_in, const int* in_sizes, int n_in,
                              void* d_out, int out_size)
{
    const float* x      = (const float*)d_in[0];   // [64,236,768]
    const float* qkv_w  = (const float*)d_in[1];   // [2304,768]
    const float* proj_w = (const float*)d_in[2];   // [768,768]
    const float* proj_b = (const float*)d_in[3];   // [768]
    float* out = (float*)d_out;                    // [64,236,768]

    float *qkv, *S, *att, *vt;
    cudaGetSymbolAddress((void**)&qkv, g_qkv);
    cudaGetSymbolAddress((void**)&S,   g_S);
    cudaGetSymbolAddress((void**)&att, g_att);
    cudaGetSymbolAddress((void**)&vt,  g_vt);

    const float scale = 0.10206207261596575f;      // 1/sqrt(96)

    // 1) qkv = x @ qkv_w^T              [15104 x 2304], K=768
    mma_gemm<false><<<dim3(118, 18, 1), 256>>>(
        x, qkv_w, nullptr, qkv,
        15104, 2304, 768, 768, 768, 2304,
        1, 0, 0, 0, 0, 0, 0, 1.0f);

    // 2) S[bh] = (Q @ K^T) * scale      512 batches, 236x236, K=96
    mma_gemm<false><<<dim3(2, 2, 512), 256>>>(
        qkv, qkv + 768, nullptr, S,
        236, 236, 96, 2304, 2304, 236,
        8, (long)236 * 2304, 96, (long)236 * 2304, 96,
        (long)8 * 236 * 236, (long)236 * 236,
        scale);

    // 3) block edits + softmax (in place)
    softmax_edit_kernel<<<dim3(236, 512), 256>>>(S);

    // 3b) V transpose
    vtrans_kernel<<<dim3(8, 3, 512), dim3(32, 8)>>>(qkv, vt);

    // 4) att[bh] = P @ vt^T             512 batches, 236x96, K=236
    mma_gemm<false><<<dim3(2, 1, 512), 256>>>(
        S, vt, nullptr, att,
        236, 96, 236, 236, 236, 768,
        8, (long)8 * 236 * 236, (long)236 * 236,
        (long)8 * 96 * 236, (long)96 * 236,
        (long)236 * 768, 96,
        1.0f);

    // 5) out = att @ proj_w^T + proj_b  [15104 x 768], K=768
    mma_gemm<true><<<dim3(118, 6, 1), 256>>>(
        att, proj_w, proj_b, out,
        15104, 768, 768, 768, 768, 768,
        1, 0, 0, 0, 0, 0, 0, 1.0f);
}

// round 6
// speedup vs baseline: 2.8899x; 1.8423x over previous
#include <cuda_runtime.h>
#include <cstdint>
#include <math.h>

// ---------------------------------------------------------------------------
// Problem: B=64, N=236, C=768, H=8, D=96.  M = B*N = 15104 = 118*128.
// Scratch (static device globals -- no runtime allocation allowed)
// ---------------------------------------------------------------------------
__device__ float g_qkv[(size_t)15104 * 2304];   // [B*N, 3C] (tf32-rounded)
__device__ float g_S[(size_t)512 * 236 * 236];  // [B*H, 236, 236]
__device__ float g_att[(size_t)15104 * 768];    // [B, N, C] (tf32-rounded)
__device__ float g_vt[(size_t)512 * 96 * 236];  // [B*H, 96, 236]
__device__ float g_xc[(size_t)15104 * 768];     // x, tf32-rounded
__device__ float g_wc[(size_t)2304 * 768];      // qkv_w, tf32-rounded
__device__ float g_pwc[(size_t)768 * 768];      // proj_w, tf32-rounded

// ---------------------------------------------------------------------------
__device__ __forceinline__ float to_tf32(float x) {
    uint32_t r;
    asm("cvt.rna.tf32.f32 %0, %1;" : "=r"(r) : "f"(x));
    return __uint_as_float(r);
}
__device__ __forceinline__ uint32_t smem_u32(const void* p) {
    uint32_t a;
    asm("{ .reg .u64 t; cvta.to.shared.u64 t, %1; cvt.u32.u64 %0, t; }" : "=r"(a) : "l"(p));
    return a;
}
__device__ __forceinline__ void mma_tf32(float* c, const uint32_t* a, const uint32_t* b) {
    asm volatile(
        "mma.sync.aligned.m16n8k8.row.col.f32.tf32.tf32.f32 "
        "{%0,%1,%2,%3}, {%4,%5,%6,%7}, {%8,%9}, {%0,%1,%2,%3};"
        : "+f"(c[0]), "+f"(c[1]), "+f"(c[2]), "+f"(c[3])
        : "r"(a[0]), "r"(a[1]), "r"(a[2]), "r"(a[3]), "r"(b[0]), "r"(b[1]));
}
// cp.async 16B with zero-fill when !pred (src-size = 0)
__device__ __forceinline__ void cpa16(uint32_t dst, const float* src, bool pred) {
    int sz = pred ? 16 : 0;
    asm volatile("cp.async.cg.shared.global [%0], [%1], 16, %2;"
                 :: "r"(dst), "l"(src), "r"(sz) : "memory");
}

// ---------------------------------------------------------------------------
// tf32 tensor-core batched NT GEMM: C[m,n] = alpha*sum_k A[m,k]*B[n,k] (+bias[n])
// Inputs MUST already be tf32-rounded fp32. 128x128x16 tile, 256 threads,
// 8 warps (4x2), warp tile 32x64, 3-stage cp.async pipeline.
// smem layout per stage: A[128][20], B[128][20] (pitch 20 floats: 16B-aligned
// rows, conflict-free fragment reads). Stage stride 5120 floats.
// ---------------------------------------------------------------------------
template<bool EPI_CVT, bool ADD_BIAS>
__global__ void __launch_bounds__(256, 2)
mma_gemm(const float* __restrict__ Ag, const float* __restrict__ Bg,
         const float* __restrict__ bias, float* __restrict__ Cg,
         int M, int N, int K, int lda, int ldb, int ldc,
         int HB, long sAb, long sAh, long sBb, long sBh, long sCb, long sCh,
         float alpha)
{
    extern __shared__ float smem[];   // 3 * 5120 floats = 61440 B

    const int z  = blockIdx.z;
    const int hb = z % HB, bb = z / HB;
    const float* A = Ag + (size_t)bb * sAb + (size_t)hb * sAh;
    const float* B = Bg + (size_t)bb * sBb + (size_t)hb * sBh;
    float*       C = Cg + (size_t)bb * sCb + (size_t)hb * sCh;

    const int bm = blockIdx.x * 128, bn = blockIdx.y * 128;
    const int tid = threadIdx.x, lane = tid & 31, wid = tid >> 5;
    const int wr = wid & 3, wc = wid >> 2;     // warp row (x32), warp col (x64)
    const int q = lane >> 2, r = lane & 3;
    const uint32_t sbase = smem_u32(smem);

    float acc[2][8][4];
#pragma unroll
    for (int t2 = 0; t2 < 2; t2++)
#pragma unroll
        for (int j = 0; j < 8; j++)
#pragma unroll
            for (int u = 0; u < 4; u++) acc[t2][j][u] = 0.0f;

    auto issue = [&](int stage, int t) {
        const int k0 = t * 16;
#pragma unroll
        for (int i = 0; i < 2; i++) {
            int cid = tid + i * 256;
            int m = cid >> 2, c4 = cid & 3;
            int gc = k0 + c4 * 4;
            // A chunk
            {
                int gr = bm + m;
                bool p = (gr < M) && (gc + 4 <= K);
                const float* src = p ? (A + (size_t)gr * lda + gc) : A;
                cpa16(sbase + (uint32_t)((stage * 5120 + m * 20 + c4 * 4) * 4), src, p);
            }
            // B chunk
            {
                int gr = bn + m;
                bool p = (gr < N) && (gc + 4 <= K);
                const float* src = p ? (B + (size_t)gr * ldb + gc) : B;
                cpa16(sbase + (uint32_t)((stage * 5120 + 2560 + m * 20 + c4 * 4) * 4), src, p);
            }
        }
    };

    auto compute = [&](int stage) {
        const float* As_ = smem + stage * 5120;
        const float* Bs_ = As_ + 2560;
#pragma unroll
        for (int ks = 0; ks < 16; ks += 8) {
            uint32_t a[2][4], b[8][2];
#pragma unroll
            for (int t2 = 0; t2 < 2; t2++) {
                int m0 = wr * 32 + t2 * 16 + q;
                a[t2][0] = __float_as_uint(As_[m0 * 20 + ks + r]);
                a[t2][1] = __float_as_uint(As_[(m0 + 8) * 20 + ks + r]);
                a[t2][2] = __float_as_uint(As_[m0 * 20 + ks + r + 4]);
                a[t2][3] = __float_as_uint(As_[(m0 + 8) * 20 + ks + r + 4]);
            }
#pragma unroll
            for (int j = 0; j < 8; j++) {
                int n0 = wc * 64 + j * 8 + q;
                b[j][0] = __float_as_uint(Bs_[n0 * 20 + ks + r]);
                b[j][1] = __float_as_uint(Bs_[n0 * 20 + ks + r + 4]);
            }
#pragma unroll
            for (int t2 = 0; t2 < 2; t2++)
#pragma unroll
                for (int j = 0; j < 8; j++)
                    mma_tf32(acc[t2][j], a[t2], b[j]);
        }
    };

    const int ntiles = (K + 15) / 16;

    issue(0, 0);
    asm volatile("cp.async.commit_group;" ::: "memory");
    if (ntiles > 1) issue(1, 1);
    asm volatile("cp.async.commit_group;" ::: "memory");

    for (int t = 0; t < ntiles; t++) {
        asm volatile("cp.async.wait_group 1;" ::: "memory");
        __syncthreads();
        if (t + 2 < ntiles) issue((t + 2) % 3, t + 2);
        asm volatile("cp.async.commit_group;" ::: "memory");
        compute(t % 3);
    }

    // epilogue (c0,c1 -> row, c2,c3 -> row+8; cols col, col+1)
#pragma unroll
    for (int t2 = 0; t2 < 2; t2++) {
#pragma unroll
        for (int j = 0; j < 8; j++) {
            int col = bn + wc * 64 + j * 8 + r * 2;
            if (col >= N) continue;
            int row0 = bm + wr * 32 + t2 * 16 + q;
            float bx = 0.f, by = 0.f;
            if (ADD_BIAS) { bx = bias[col]; by = bias[col + 1]; }
            if (row0 < M) {
                float2 v;
                v.x = acc[t2][j][0] * alpha + bx;
                v.y = acc[t2][j][1] * alpha + by;
                if (EPI_CVT) { v.x = to_tf32(v.x); v.y = to_tf32(v.y); }
                *reinterpret_cast<float2*>(C + (size_t)row0 * ldc + col) = v;
            }
            if (row0 + 8 < M) {
                float2 v;
                v.x = acc[t2][j][2] * alpha + bx;
                v.y = acc[t2][j][3] * alpha + by;
                if (EPI_CVT) { v.x = to_tf32(v.x); v.y = to_tf32(v.y); }
                *reinterpret_cast<float2*>(C + (size_t)(row0 + 8) * ldc + col) = v;
            }
        }
    }
}

// ---------------------------------------------------------------------------
// Elementwise tf32 rounding (float4 grid-stride)
// ---------------------------------------------------------------------------
__global__ void cvt_kernel(const float* __restrict__ in, float* __restrict__ out, int n4)
{
    int i = blockIdx.x * blockDim.x + threadIdx.x;
    if (i < n4) {
        float4 v = reinterpret_cast<const float4*>(in)[i];
        v.x = to_tf32(v.x); v.y = to_tf32(v.y);
        v.z = to_tf32(v.z); v.w = to_tf32(v.w);
        reinterpret_cast<float4*>(out)[i] = v;
    }
}

// ---------------------------------------------------------------------------
// V transpose: vt[bh][d][t] = qkv[(b*236+t)*2304 + 1536 + h*96 + d]
// ---------------------------------------------------------------------------
__global__ void vtrans_kernel(const float* __restrict__ qkv, float* __restrict__ vt)
{
    __shared__ float t[32][33];
    const int bh = blockIdx.z;
    const int b = bh >> 3, h = bh & 7;
    const int t0 = blockIdx.x * 32;
    const int d0 = blockIdx.y * 32;
    const int tx = threadIdx.x, ty = threadIdx.y;

#pragma unroll
    for (int r = ty; r < 32; r += 8) {
        int tok = t0 + r;
        int d = d0 + tx;
        float v = 0.f;
        if (tok < 236)
            v = qkv[(size_t)(b * 236 + tok) * 2304 + 1536 + h * 96 + d];
        t[r][tx] = v;
    }
    __syncthreads();
#pragma unroll
    for (int r = ty; r < 32; r += 8) {
        int d = d0 + r;
        int tok = t0 + tx;
        if (tok < 236)
            vt[((size_t)bh * 96 + d) * 236 + tok] = t[tx][r];
    }
}

// ---------------------------------------------------------------------------
// Block edits + softmax (one 256-thread CTA per attention row).
// Output probabilities are tf32-rounded (they feed the PV mma directly).
// ---------------------------------------------------------------------------
__global__ void softmax_edit_kernel(float* __restrict__ S)
{
    const int r  = blockIdx.x;   // 0..235
    const int bh = blockIdx.y;   // 0..511
    float* srow = S + ((size_t)bh * 236 + r) * 236;
    const int c = threadIdx.x;

    float v = -1e30f;
    if (c < 236) {
        float s;
        if (r < 196) {
            if (c >= 216)      s = srow[c - 20];      // copy uses PRE-bias values
            else if (c >= 196) s = srow[c] - 100.0f;
            else               s = srow[c];
        } else if (r < 216) {
            s = srow[c] - ((c >= 216) ? 100.0f : 0.0f);
        } else {
            s = srow[c] - ((c >= 196 && c < 216) ? 100.0f : 0.0f);
        }
        v = s;
    }

    __shared__ float red[8];
    float m = v;
#pragma unroll
    for (int o = 16; o > 0; o >>= 1) m = fmaxf(m, __shfl_xor_sync(0xffffffffu, m, o));
    if ((c & 31) == 0) red[c >> 5] = m;
    __syncthreads();
    float mx = fmaxf(fmaxf(fmaxf(red[0], red[1]), fmaxf(red[2], red[3])),
                     fmaxf(fmaxf(red[4], red[5]), fmaxf(red[6], red[7])));

    float e = (c < 236) ? expf(v - mx) : 0.0f;
    float ssum = e;
#pragma unroll
    for (int o = 16; o > 0; o >>= 1) ssum += __shfl_xor_sync(0xffffffffu, ssum, o);
    __syncthreads();
    if ((c & 31) == 0) red[c >> 5] = ssum;
    __syncthreads();
    float tot = red[0] + red[1] + red[2] + red[3] + red[4] + red[5] + red[6] + red[7];

    if (c < 236) srow[c] = to_tf32(e / tot);
}

// ---------------------------------------------------------------------------
extern "C" void kernel_launch(void* const* d_in, const int* in_sizes, int n_in,
                              void* d_out, int out_size)
{
    const float* x      = (const float*)d_in[0];   // [64,236,768]
    const float* qkv_w  = (const float*)d_in[1];   // [2304,768]
    const float* proj_w = (const float*)d_in[2];   // [768,768]
    const float* proj_b = (const float*)d_in[3];   // [768]
    float* out = (float*)d_out;                    // [64,236,768]

    float *qkv, *S, *att, *vt, *xc, *wcv, *pwc;
    cudaGetSymbolAddress((void**)&qkv, g_qkv);
    cudaGetSymbolAddress((void**)&S,   g_S);
    cudaGetSymbolAddress((void**)&att, g_att);
    cudaGetSymbolAddress((void**)&vt,  g_vt);
    cudaGetSymbolAddress((void**)&xc,  g_xc);
    cudaGetSymbolAddress((void**)&wcv, g_wc);
    cudaGetSymbolAddress((void**)&pwc, g_pwc);

    const int SMEM = 3 * 5120 * 4;   // 61440 B
    cudaFuncSetAttribute(mma_gemm<true,  false>, cudaFuncAttributeMaxDynamicSharedMemorySize, SMEM);
    cudaFuncSetAttribute(mma_gemm<false, false>, cudaFuncAttributeMaxDynamicSharedMemorySize, SMEM);
    cudaFuncSetAttribute(mma_gemm<false, true>,  cudaFuncAttributeMaxDynamicSharedMemorySize, SMEM);

    const float scale = 0.10206207261596575f;      // 1/sqrt(96)

    // 0) pre-round inputs to tf32
    cvt_kernel<<<(15104 * 768 / 4 + 255) / 256, 256>>>(x, xc, 15104 * 768 / 4);
    cvt_kernel<<<(2304 * 768 / 4 + 255) / 256, 256>>>(qkv_w, wcv, 2304 * 768 / 4);
    cvt_kernel<<<(768 * 768 / 4 + 255) / 256, 256>>>(proj_w, pwc, 768 * 768 / 4);

    // 1) qkv = x @ qkv_w^T              [15104 x 2304], K=768  (epilogue tf32)
    mma_gemm<true, false><<<dim3(118, 18, 1), 256, SMEM>>>(
        xc, wcv, nullptr, qkv,
        15104, 2304, 768, 768, 768, 2304,
        1, 0, 0, 0, 0, 0, 0, 1.0f);

    // 2) S[bh] = (Q @ K^T) * scale      512 batches, 236x236, K=96 (fp32 logits)
    mma_gemm<false, false><<<dim3(2, 2, 512), 256, SMEM>>>(
        qkv, qkv + 768, nullptr, S,
        236, 236, 96, 2304, 2304, 236,
        8, (long)236 * 2304, 96, (long)236 * 2304, 96,
        (long)8 * 236 * 236, (long)236 * 236,
        scale);

    // 3) block edits + softmax (in place, tf32-rounded output)
    softmax_edit_kernel<<<dim3(236, 512), 256>>>(S);

    // 3b) V transpose
    vtrans_kernel<<<dim3(8, 3, 512), dim3(32, 8)>>>(qkv, vt);

    // 4) att[bh] = P @ vt^T             512 batches, 236x96, K=236 (epilogue tf32)
    mma_gemm<true, false><<<dim3(2, 1, 512), 256, SMEM>>>(
        S, vt, nullptr, att,
        236, 96, 236, 236, 236, 768,
        8, (long)8 * 236 * 236, (long)236 * 236,
        (long)8 * 96 * 236, (long)96 * 236,
        (long)236 * 768, 96,
        1.0f);

    // 5) out = att @ proj_w^T + proj_b  [15104 x 768], K=768 (fp32 output)
    mma_gemm<false, true><<<dim3(118, 6, 1), 256, SMEM>>>(
        att, pwc, proj_b, out,
        15104, 768, 768, 768, 768, 768,
        1, 0, 0, 0, 0, 0, 0, 1.0f);
}

// round 8
// speedup vs baseline: 3.0616x; 1.0594x over previous
#include <cuda_runtime.h>
#include <cstdint>
#include <math.h>

// ---------------------------------------------------------------------------
// Problem: B=64, N=236, C=768, H=8, D=96.  M = B*N = 15104 = 118*128.
// Scratch (static device globals -- no runtime allocation allowed)
// ---------------------------------------------------------------------------
__device__ float g_qkv[(size_t)15104 * 2304];   // [B*N, 3C] (tf32-rounded)
__device__ float g_S[(size_t)512 * 236 * 236];  // [B*H, 236, 236]
__device__ float g_att[(size_t)15104 * 768];    // [B, N, C] (tf32-rounded)
__device__ float g_vt[(size_t)512 * 96 * 236];  // [B*H, 96, 236]
__device__ float g_xc[(size_t)15104 * 768];     // x, tf32-rounded
__device__ float g_wc[(size_t)2304 * 768];      // qkv_w, tf32-rounded
__device__ float g_pwc[(size_t)768 * 768];      // proj_w, tf32-rounded

// ---------------------------------------------------------------------------
__device__ __forceinline__ float to_tf32(float x) {
    uint32_t r;
    asm("cvt.rna.tf32.f32 %0, %1;" : "=r"(r) : "f"(x));
    return __uint_as_float(r);
}
__device__ __forceinline__ uint32_t smem_u32(const void* p) {
    uint32_t a;
    asm("{ .reg .u64 t; cvta.to.shared.u64 t, %1; cvt.u32.u64 %0, t; }" : "=r"(a) : "l"(p));
    return a;
}
__device__ __forceinline__ void mma_tf32(float* c, const uint32_t* a, const uint32_t* b) {
    asm volatile(
        "mma.sync.aligned.m16n8k8.row.col.f32.tf32.tf32.f32 "
        "{%0,%1,%2,%3}, {%4,%5,%6,%7}, {%8,%9}, {%0,%1,%2,%3};"
        : "+f"(c[0]), "+f"(c[1]), "+f"(c[2]), "+f"(c[3])
        : "r"(a[0]), "r"(a[1]), "r"(a[2]), "r"(a[3]), "r"(b[0]), "r"(b[1]));
}
// cp.async 16B with zero-fill when !pred (src-size = 0)
__device__ __forceinline__ void cpa16(uint32_t dst, const float* src, bool pred) {
    int sz = pred ? 16 : 0;
    asm volatile("cp.async.cg.shared.global [%0], [%1], 16, %2;"
                 :: "r"(dst), "l"(src), "r"(sz) : "memory");
}

// ---------------------------------------------------------------------------
// tf32 tensor-core batched NT GEMM: C[m,n] = alpha*sum_k A[m,k]*B[n,k] (+bias[n])
// Inputs MUST already be tf32-rounded fp32. 128x128x32 tile, 256 threads,
// 8 warps (4x2), warp tile 32x64, 2-stage cp.async pipeline.
// smem per stage: A[128][36], B[128][36] (pitch 36 floats: 16B-aligned rows,
// conflict-free fragment reads: bank = 4q + r + k, all 32 distinct).
// Stage stride 9216 floats (36864 B); 2 stages = 73728 B.
// ---------------------------------------------------------------------------
template<bool EPI_CVT, bool ADD_BIAS>
__global__ void __launch_bounds__(256, 2)
mma_gemm(const float* __restrict__ Ag, const float* __restrict__ Bg,
         const float* __restrict__ bias, float* __restrict__ Cg,
         int M, int N, int K, int lda, int ldb, int ldc,
         int HB, long sAb, long sAh, long sBb, long sBh, long sCb, long sCh,
         float alpha)
{
    extern __shared__ float smem[];   // 2 * 9216 floats = 73728 B

    const int z  = blockIdx.z;
    const int hb = z % HB, bb = z / HB;
    const float* A = Ag + (size_t)bb * sAb + (size_t)hb * sAh;
    const float* B = Bg + (size_t)bb * sBb + (size_t)hb * sBh;
    float*       C = Cg + (size_t)bb * sCb + (size_t)hb * sCh;

    const int bm = blockIdx.x * 128, bn = blockIdx.y * 128;
    const int tid = threadIdx.x, lane = tid & 31, wid = tid >> 5;
    const int wr = wid & 3, wc = wid >> 2;     // warp row (x32), warp col (x64)
    const int q = lane >> 2, r = lane & 3;
    const uint32_t sbase = smem_u32(smem);

    float acc[2][8][4];
#pragma unroll
    for (int t2 = 0; t2 < 2; t2++)
#pragma unroll
        for (int j = 0; j < 8; j++)
#pragma unroll
            for (int u = 0; u < 4; u++) acc[t2][j][u] = 0.0f;

    // one BK=32 tile: A 128x32 = 1024 16B-chunks, B same -> 4+4 per thread
    auto issue = [&](int stage, int t) {
        const int k0 = t * 32;
#pragma unroll
        for (int i = 0; i < 4; i++) {
            int cid = tid + i * 256;
            int m = cid >> 3, c8 = cid & 7;
            int gc = k0 + c8 * 4;
            {   // A chunk
                int gr = bm + m;
                bool p = (gr < M) && (gc + 4 <= K);
                const float* src = p ? (A + (size_t)gr * lda + gc) : A;
                cpa16(sbase + (uint32_t)((stage * 9216 + m * 36 + c8 * 4) * 4), src, p);
            }
            {   // B chunk
                int gr = bn + m;
                bool p = (gr < N) && (gc + 4 <= K);
                const float* src = p ? (B + (size_t)gr * ldb + gc) : B;
                cpa16(sbase + (uint32_t)((stage * 9216 + 4608 + m * 36 + c8 * 4) * 4), src, p);
            }
        }
    };

    auto compute = [&](int stage) {
        const float* As_ = smem + stage * 9216;
        const float* Bs_ = As_ + 4608;
#pragma unroll
        for (int ks = 0; ks < 32; ks += 8) {
            uint32_t a[2][4], b[8][2];
#pragma unroll
            for (int t2 = 0; t2 < 2; t2++) {
                int m0 = wr * 32 + t2 * 16 + q;
                a[t2][0] = __float_as_uint(As_[m0 * 36 + ks + r]);
                a[t2][1] = __float_as_uint(As_[(m0 + 8) * 36 + ks + r]);
                a[t2][2] = __float_as_uint(As_[m0 * 36 + ks + r + 4]);
                a[t2][3] = __float_as_uint(As_[(m0 + 8) * 36 + ks + r + 4]);
            }
#pragma unroll
            for (int j = 0; j < 8; j++) {
                int n0 = wc * 64 + j * 8 + q;
                b[j][0] = __float_as_uint(Bs_[n0 * 36 + ks + r]);
                b[j][1] = __float_as_uint(Bs_[n0 * 36 + ks + r + 4]);
            }
#pragma unroll
            for (int t2 = 0; t2 < 2; t2++)
#pragma unroll
                for (int j = 0; j < 8; j++)
                    mma_tf32(acc[t2][j], a[t2], b[j]);
        }
    };

    const int ntiles = (K + 31) / 32;

    issue(0, 0);
    asm volatile("cp.async.commit_group;" ::: "memory");

    for (int t = 0; t < ntiles; t++) {
        if (t + 1 < ntiles) issue((t + 1) & 1, t + 1);
        asm volatile("cp.async.commit_group;" ::: "memory");
        asm volatile("cp.async.wait_group 1;" ::: "memory");   // tile t ready
        __syncthreads();
        compute(t & 1);
        __syncthreads();   // all reads of buffer t&1 done before it is refilled
    }

    // epilogue (c0,c1 -> row, c2,c3 -> row+8; cols col, col+1)
#pragma unroll
    for (int t2 = 0; t2 < 2; t2++) {
#pragma unroll
        for (int j = 0; j < 8; j++) {
            int col = bn + wc * 64 + j * 8 + r * 2;
            if (col >= N) continue;
            int row0 = bm + wr * 32 + t2 * 16 + q;
            float bx = 0.f, by = 0.f;
            if (ADD_BIAS) { bx = bias[col]; by = bias[col + 1]; }
            if (row0 < M) {
                float2 v;
                v.x = acc[t2][j][0] * alpha + bx;
                v.y = acc[t2][j][1] * alpha + by;
                if (EPI_CVT) { v.x = to_tf32(v.x); v.y = to_tf32(v.y); }
                *reinterpret_cast<float2*>(C + (size_t)row0 * ldc + col) = v;
            }
            if (row0 + 8 < M) {
                float2 v;
                v.x = acc[t2][j][2] * alpha + bx;
                v.y = acc[t2][j][3] * alpha + by;
                if (EPI_CVT) { v.x = to_tf32(v.x); v.y = to_tf32(v.y); }
                *reinterpret_cast<float2*>(C + (size_t)(row0 + 8) * ldc + col) = v;
            }
        }
    }
}

// ---------------------------------------------------------------------------
// Elementwise tf32 rounding (float4)
// ---------------------------------------------------------------------------
__global__ void cvt_kernel(const float* __restrict__ in, float* __restrict__ out, int n4)
{
    int i = blockIdx.x * blockDim.x + threadIdx.x;
    if (i < n4) {
        float4 v = reinterpret_cast<const float4*>(in)[i];
        v.x = to_tf32(v.x); v.y = to_tf32(v.y);
        v.z = to_tf32(v.z); v.w = to_tf32(v.w);
        reinterpret_cast<float4*>(out)[i] = v;
    }
}

// ---------------------------------------------------------------------------
// V transpose: vt[bh][d][t] = qkv[(b*236+t)*2304 + 1536 + h*96 + d]
// ---------------------------------------------------------------------------
__global__ void vtrans_kernel(const float* __restrict__ qkv, float* __restrict__ vt)
{
    __shared__ float t[32][33];
    const int bh = blockIdx.z;
    const int b = bh >> 3, h = bh & 7;
    const int t0 = blockIdx.x * 32;
    const int d0 = blockIdx.y * 32;
    const int tx = threadIdx.x, ty = threadIdx.y;

#pragma unroll
    for (int r = ty; r < 32; r += 8) {
        int tok = t0 + r;
        int d = d0 + tx;
        float v = 0.f;
        if (tok < 236)
            v = qkv[(size_t)(b * 236 + tok) * 2304 + 1536 + h * 96 + d];
        t[r][tx] = v;
    }
    __syncthreads();
#pragma unroll
    for (int r = ty; r < 32; r += 8) {
        int d = d0 + r;
        int tok = t0 + tx;
        if (tok < 236)
            vt[((size_t)bh * 96 + d) * 236 + tok] = t[tx][r];
    }
}

// ---------------------------------------------------------------------------
// Block edits + softmax (one 256-thread CTA per attention row).
// Output probabilities tf32-rounded (they feed the PV mma directly).
// ---------------------------------------------------------------------------
__global__ void softmax_edit_kernel(float* __restrict__ S)
{
    const int r  = blockIdx.x;   // 0..235
    const int bh = blockIdx.y;   // 0..511
    float* srow = S + ((size_t)bh * 236 + r) * 236;
    const int c = threadIdx.x;

    float v = -1e30f;
    if (c < 236) {
        float s;
        if (r < 196) {
            if (c >= 216)      s = srow[c - 20];      // copy uses PRE-bias values
            else if (c >= 196) s = srow[c] - 100.0f;
            else               s = srow[c];
        } else if (r < 216) {
            s = srow[c] - ((c >= 216) ? 100.0f : 0.0f);
        } else {
            s = srow[c] - ((c >= 196 && c < 216) ? 100.0f : 0.0f);
        }
        v = s;
    }

    __shared__ float red[8];
    float m = v;
#pragma unroll
    for (int o = 16; o > 0; o >>= 1) m = fmaxf(m, __shfl_xor_sync(0xffffffffu, m, o));
    if ((c & 31) == 0) red[c >> 5] = m;
    __syncthreads();
    float mx = fmaxf(fmaxf(fmaxf(red[0], red[1]), fmaxf(red[2], red[3])),
                     fmaxf(fmaxf(red[4], red[5]), fmaxf(red[6], red[7])));

    float e = (c < 236) ? expf(v - mx) : 0.0f;
    float ssum = e;
#pragma unroll
    for (int o = 16; o > 0; o >>= 1) ssum += __shfl_xor_sync(0xffffffffu, ssum, o);
    __syncthreads();
    if ((c & 31) == 0) red[c >> 5] = ssum;
    __syncthreads();
    float tot = red[0] + red[1] + red[2] + red[3] + red[4] + red[5] + red[6] + red[7];

    if (c < 236) srow[c] = to_tf32(e / tot);
}

// ---------------------------------------------------------------------------
extern "C" void kernel_launch(void* const* d_in, const int* in_sizes, int n_in,
                              void* d_out, int out_size)
{
    const float* x      = (const float*)d_in[0];   // [64,236,768]
    const float* qkv_w  = (const float*)d_in[1];   // [2304,768]
    const float* proj_w = (const float*)d_in[2];   // [768,768]
    const float* proj_b = (const float*)d_in[3];   // [768]
    float* out = (float*)d_out;                    // [64,236,768]

    float *qkv, *S, *att, *vt, *xc, *wcv, *pwc;
    cudaGetSymbolAddress((void**)&qkv, g_qkv);
    cudaGetSymbolAddress((void**)&S,   g_S);
    cudaGetSymbolAddress((void**)&att, g_att);
    cudaGetSymbolAddress((void**)&vt,  g_vt);
    cudaGetSymbolAddress((void**)&xc,  g_xc);
    cudaGetSymbolAddress((void**)&wcv, g_wc);
    cudaGetSymbolAddress((void**)&pwc, g_pwc);

    const int SMEM = 2 * 9216 * 4;   // 73728 B
    cudaFuncSetAttribute(mma_gemm<true,  false>, cudaFuncAttributeMaxDynamicSharedMemorySize, SMEM);
    cudaFuncSetAttribute(mma_gemm<false, false>, cudaFuncAttributeMaxDynamicSharedMemorySize, SMEM);
    cudaFuncSetAttribute(mma_gemm<false, true>,  cudaFuncAttributeMaxDynamicSharedMemorySize, SMEM);

    const float scale = 0.10206207261596575f;      // 1/sqrt(96)

    // 0) pre-round inputs to tf32
    cvt_kernel<<<(15104 * 768 / 4 + 255) / 256, 256>>>(x, xc, 15104 * 768 / 4);
    cvt_kernel<<<(2304 * 768 / 4 + 255) / 256, 256>>>(qkv_w, wcv, 2304 * 768 / 4);
    cvt_kernel<<<(768 * 768 / 4 + 255) / 256, 256>>>(proj_w, pwc, 768 * 768 / 4);

    // 1) qkv = x @ qkv_w^T              [15104 x 2304], K=768  (epilogue tf32)
    mma_gemm<true, false><<<dim3(118, 18, 1), 256, SMEM>>>(
        xc, wcv, nullptr, qkv,
        15104, 2304, 768, 768, 768, 2304,
        1, 0, 0, 0, 0, 0, 0, 1.0f);

    // 2) S[bh] = (Q @ K^T) * scale      512 batches, 236x236, K=96 (fp32 logits)
    mma_gemm<false, false><<<dim3(2, 2, 512), 256, SMEM>>>(
        qkv, qkv + 768, nullptr, S,
        236, 236, 96, 2304, 2304, 236,
        8, (long)236 * 2304, 96, (long)236 * 2304, 96,
        (long)8 * 236 * 236, (long)236 * 236,
        scale);

    // 3) block edits + softmax (in place, tf32-rounded output)
    softmax_edit_kernel<<<dim3(236, 512), 256>>>(S);

    // 3b) V transpose
    vtrans_kernel<<<dim3(8, 3, 512), dim3(32, 8)>>>(qkv, vt);

    // 4) att[bh] = P @ vt^T             512 batches, 236x96, K=236 (epilogue tf32)
    mma_gemm<true, false><<<dim3(2, 1, 512), 256, SMEM>>>(
        S, vt, nullptr, att,
        236, 96, 236, 236, 236, 768,
        8, (long)8 * 236 * 236, (long)236 * 236,
        (long)8 * 96 * 236, (long)96 * 236,
        (long)236 * 768, 96,
        1.0f);

    // 5) out = att @ proj_w^T + proj_b  [15104 x 768], K=768 (fp32 output)
    mma_gemm<false, true><<<dim3(118, 6, 1), 256, SMEM>>>(
        att, pwc, proj_b, out,
        15104, 768, 768, 768, 768, 768,
        1, 0, 0, 0, 0, 0, 0, 1.0f);
}

// round 10
// speedup vs baseline: 4.3563x; 1.4229x over previous
#include <cuda_runtime.h>
#include <cuda_fp16.h>
#include <cstdint>
#include <math.h>

// ---------------------------------------------------------------------------
// Problem: B=64, N=236, C=768, H=8, D=96.  M = B*N = 15104 = 118*128.
// Scratch (static device globals -- no runtime allocation allowed)
// ---------------------------------------------------------------------------
__device__ __half g_qkvh[(size_t)15104 * 2304];  // [B*N, 3C] fp16
__device__ float  g_S[(size_t)512 * 236 * 236];  // [B*H, 236, 236] fp32 logits
__device__ __half g_P[(size_t)512 * 236 * 240];  // probs fp16, K-padded to 240
__device__ __half g_vth[(size_t)512 * 96 * 240]; // V^T fp16, padded to 240
__device__ __half g_atth[(size_t)15104 * 768];   // attention out fp16
__device__ __half g_xh[(size_t)15104 * 768];     // x fp16
__device__ __half g_wh[(size_t)2304 * 768];      // qkv_w fp16
__device__ __half g_pwh[(size_t)768 * 768];      // proj_w fp16

// ---------------------------------------------------------------------------
__device__ __forceinline__ uint32_t smem_u32(const void* p) {
    uint32_t a;
    asm("{ .reg .u64 t; cvta.to.shared.u64 t, %1; cvt.u32.u64 %0, t; }" : "=r"(a) : "l"(p));
    return a;
}
__device__ __forceinline__ void mma_f16(float* c, const uint32_t* a, const uint32_t* b) {
    asm volatile(
        "mma.sync.aligned.m16n8k16.row.col.f32.f16.f16.f32 "
        "{%0,%1,%2,%3}, {%4,%5,%6,%7}, {%8,%9}, {%0,%1,%2,%3};"
        : "+f"(c[0]), "+f"(c[1]), "+f"(c[2]), "+f"(c[3])
        : "r"(a[0]), "r"(a[1]), "r"(a[2]), "r"(a[3]), "r"(b[0]), "r"(b[1]));
}
#define LDMX4(r, addr) \
    asm volatile("ldmatrix.sync.aligned.m8n8.x4.shared.b16 {%0,%1,%2,%3}, [%4];" \
                 : "=r"((r)[0]), "=r"((r)[1]), "=r"((r)[2]), "=r"((r)[3]) : "r"(addr))
// cp.async 16B; when !pred copies 0 source bytes -> dst 16B zero-filled
__device__ __forceinline__ void cpa16(uint32_t dst, const void* src, bool pred) {
    int sz = pred ? 16 : 0;
    asm volatile("cp.async.cg.shared.global [%0], [%1], 16, %2;"
                 :: "r"(dst), "l"(src), "r"(sz) : "memory");
}

// ---------------------------------------------------------------------------
// fp16 tensor-core batched NT GEMM: C[m,n] = alpha*sum_k A[m,k]*B[n,k] (+bias[n])
// A,B fp16; accumulate fp32; C fp32 or fp16 (OUT_HALF).
// 128x128x32 tile, 256 threads, 8 warps (4x2), warp tile 32x64,
// 2-stage cp.async pipeline, ldmatrix fragment loads.
// smem per stage per operand: 128 rows x 40 halves (80B pitch) = 10240 B.
// Stage stride 20480 B; 2 stages = 40960 B.
// ---------------------------------------------------------------------------
template<bool OUT_HALF, bool ADD_BIAS>
__global__ void __launch_bounds__(256, 2)
hgemm(const __half* __restrict__ Ag, const __half* __restrict__ Bg,
      const float* __restrict__ bias, void* __restrict__ Cv,
      int M, int N, int K, int lda, int ldb, int ldc,
      int HB, long sAb, long sAh, long sBb, long sBh, long sCb, long sCh,
      float alpha)
{
    extern __shared__ __half smem[];   // 20480 halves = 40960 B

    const int z  = blockIdx.z;
    const int hb = z % HB, bb = z / HB;
    const __half* A = Ag + (size_t)bb * sAb + (size_t)hb * sAh;
    const __half* B = Bg + (size_t)bb * sBb + (size_t)hb * sBh;

    const int bm = blockIdx.x * 128, bn = blockIdx.y * 128;
    const int tid = threadIdx.x, lane = tid & 31, wid = tid >> 5;
    const int wr = wid & 3, wc = wid >> 2;     // warp row (x32), warp col (x64)
    const int q = lane >> 2, r = lane & 3;
    const uint32_t sbase = smem_u32(smem);

    // ldmatrix lane address components
    const int lt = lane >> 3, li = lane & 7;
    const int aRow = wr * 32 + (lt & 1) * 8 + li;    // + t2*16
    const int aCol = (lt >> 1) * 16;                  // bytes; + ks*2
    const int bRow = wc * 64 + (lt >> 1) * 8 + li;    // + jp*16
    const int bCol = (lt & 1) * 16;                   // bytes; + ks*2

    float acc[2][8][4];
#pragma unroll
    for (int t2 = 0; t2 < 2; t2++)
#pragma unroll
        for (int j = 0; j < 8; j++)
#pragma unroll
            for (int u = 0; u < 4; u++) acc[t2][j][u] = 0.0f;

    // one BK=32 tile per operand: 128 rows x 4 chunks(8 halves) = 512 chunks
    auto issue = [&](int stage, int t) {
        const int k0 = t * 32;
#pragma unroll
        for (int i = 0; i < 2; i++) {   // A
            int cid = tid + i * 256;
            int m = cid >> 2, c8 = cid & 3;
            int gc = k0 + c8 * 8;
            int gr = bm + m;
            bool p = (gr < M) && (gc + 8 <= K);
            const __half* src = p ? (A + (size_t)gr * lda + gc) : A;
            cpa16(sbase + (uint32_t)(stage * 20480 + m * 80 + c8 * 16), src, p);
        }
#pragma unroll
        for (int i = 0; i < 2; i++) {   // B
            int cid = tid + i * 256;
            int m = cid >> 2, c8 = cid & 3;
            int gc = k0 + c8 * 8;
            int gr = bn + m;
            bool p = (gr < N) && (gc + 8 <= K);
            const __half* src = p ? (B + (size_t)gr * ldb + gc) : B;
            cpa16(sbase + (uint32_t)(stage * 20480 + 10240 + m * 80 + c8 * 16), src, p);
        }
    };

    auto compute = [&](int stage) {
        const uint32_t baseA = sbase + stage * 20480;
        const uint32_t baseB = baseA + 10240;
#pragma unroll
        for (int ks = 0; ks < 32; ks += 16) {
            uint32_t a[2][4], b[4][4];
#pragma unroll
            for (int t2 = 0; t2 < 2; t2++)
                LDMX4(a[t2], baseA + (uint32_t)((aRow + t2 * 16) * 80 + aCol + ks * 2));
#pragma unroll
            for (int jp = 0; jp < 4; jp++)
                LDMX4(b[jp], baseB + (uint32_t)((bRow + jp * 16) * 80 + bCol + ks * 2));
#pragma unroll
            for (int t2 = 0; t2 < 2; t2++)
#pragma unroll
                for (int j = 0; j < 8; j++) {
                    uint32_t bb2[2] = { b[j >> 1][(j & 1) * 2], b[j >> 1][(j & 1) * 2 + 1] };
                    mma_f16(acc[t2][j], a[t2], bb2);
                }
        }
    };

    const int ntiles = (K + 31) / 32;

    issue(0, 0);
    asm volatile("cp.async.commit_group;" ::: "memory");

    for (int t = 0; t < ntiles; t++) {
        if (t + 1 < ntiles) issue((t + 1) & 1, t + 1);
        asm volatile("cp.async.commit_group;" ::: "memory");
        asm volatile("cp.async.wait_group 1;" ::: "memory");   // tile t ready
        __syncthreads();
        compute(t & 1);
        __syncthreads();   // reads done before buffer refilled
    }

    // epilogue: c0,c1 -> (row, col..col+1), c2,c3 -> (row+8, ...)
#pragma unroll
    for (int t2 = 0; t2 < 2; t2++) {
#pragma unroll
        for (int j = 0; j < 8; j++) {
            int col = bn + wc * 64 + j * 8 + r * 2;
            if (col >= N) continue;
            int row0 = bm + wr * 32 + t2 * 16 + q;
            float bx = 0.f, by = 0.f;
            if (ADD_BIAS) { bx = bias[col]; by = bias[col + 1]; }
#pragma unroll
            for (int h = 0; h < 2; h++) {
                int row = row0 + h * 8;
                if (row >= M) continue;
                float vx = acc[t2][j][h * 2 + 0] * alpha + bx;
                float vy = acc[t2][j][h * 2 + 1] * alpha + by;
                if (OUT_HALF) {
                    __half2* dst = reinterpret_cast<__half2*>(
                        (__half*)Cv + (size_t)bb * sCb + (size_t)hb * sCh + (size_t)row * ldc + col);
                    *dst = __floats2half2_rn(vx, vy);
                } else {
                    float2* dst = reinterpret_cast<float2*>(
                        (float*)Cv + (size_t)bb * sCb + (size_t)hb * sCh + (size_t)row * ldc + col);
                    *dst = make_float2(vx, vy);
                }
            }
        }
    }
}

// ---------------------------------------------------------------------------
// fp32 -> fp16 conversion (4 floats / thread)
// ---------------------------------------------------------------------------
__global__ void cvt_h(const float* __restrict__ in, __half* __restrict__ out, int n4)
{
    int i = blockIdx.x * blockDim.x + threadIdx.x;
    if (i < n4) {
        float4 v = reinterpret_cast<const float4*>(in)[i];
        uint2 u;
        __half2 h0 = __floats2half2_rn(v.x, v.y);
        __half2 h1 = __floats2half2_rn(v.z, v.w);
        u.x = *reinterpret_cast<uint32_t*>(&h0);
        u.y = *reinterpret_cast<uint32_t*>(&h1);
        reinterpret_cast<uint2*>(out)[i] = u;
    }
}

// ---------------------------------------------------------------------------
// V transpose fp16: vth[bh][d][tok] = qkvh[(b*236+tok)*2304 + 1536 + h*96 + d]
// Output pitch 240 (tok 236..239 zero-filled).
// ---------------------------------------------------------------------------
__global__ void vtrans_kernel(const __half* __restrict__ qkvh, __half* __restrict__ vt)
{
    __shared__ float t[32][33];
    const int bh = blockIdx.z;
    const int b = bh >> 3, h = bh & 7;
    const int t0 = blockIdx.x * 32;
    const int d0 = blockIdx.y * 32;
    const int tx = threadIdx.x, ty = threadIdx.y;

#pragma unroll
    for (int r = ty; r < 32; r += 8) {
        int tok = t0 + r;
        int d = d0 + tx;
        float v = 0.f;
        if (tok < 236)
            v = __half2float(qkvh[(size_t)(b * 236 + tok) * 2304 + 1536 + h * 96 + d]);
        t[r][tx] = v;
    }
    __syncthreads();
#pragma unroll
    for (int r = ty; r < 32; r += 8) {
        int d = d0 + r;
        int tok = t0 + tx;
        if (tok < 240)
            vt[((size_t)bh * 96 + d) * 240 + tok] =
                (tok < 236) ? __float2half_rn(t[tx][r]) : __float2half_rn(0.f);
    }
}

// ---------------------------------------------------------------------------
// Block edits + softmax. Reads fp32 logits S[bh][236][236], writes fp16
// probabilities P[bh][236][240] (cols 236..239 zeroed).
// ---------------------------------------------------------------------------
__global__ void softmax_edit_kernel(const float* __restrict__ S, __half* __restrict__ P)
{
    const int r  = blockIdx.x;   // 0..235
    const int bh = blockIdx.y;   // 0..511
    const float* srow = S + ((size_t)bh * 236 + r) * 236;
    __half* prow = P + ((size_t)bh * 236 + r) * 240;
    const int c = threadIdx.x;

    float v = -1e30f;
    if (c < 236) {
        float s;
        if (r < 196) {
            if (c >= 216)      s = srow[c - 20];      // copy uses PRE-bias values
            else if (c >= 196) s = srow[c] - 100.0f;
            else               s = srow[c];
        } else if (r < 216) {
            s = srow[c] - ((c >= 216) ? 100.0f : 0.0f);
        } else {
            s = srow[c] - ((c >= 196 && c < 216) ? 100.0f : 0.0f);
        }
        v = s;
    }

    __shared__ float red[8];
    float m = v;
#pragma unroll
    for (int o = 16; o > 0; o >>= 1) m = fmaxf(m, __shfl_xor_sync(0xffffffffu, m, o));
    if ((c & 31) == 0) red[c >> 5] = m;
    __syncthreads();
    float mx = fmaxf(fmaxf(fmaxf(red[0], red[1]), fmaxf(red[2], red[3])),
                     fmaxf(fmaxf(red[4], red[5]), fmaxf(red[6], red[7])));

    float e = (c < 236) ? expf(v - mx) : 0.0f;
    float ssum = e;
#pragma unroll
    for (int o = 16; o > 0; o >>= 1) ssum += __shfl_xor_sync(0xffffffffu, ssum, o);
    __syncthreads();
    if ((c & 31) == 0) red[c >> 5] = ssum;
    __syncthreads();
    float tot = red[0] + red[1] + red[2] + red[3] + red[4] + red[5] + red[6] + red[7];

    if (c < 240) prow[c] = (c < 236) ? __float2half_rn(e / tot) : __float2half_rn(0.f);
}

// ---------------------------------------------------------------------------
extern "C" void kernel_launch(void* const* d_in, const int* in_sizes, int n_in,
                              void* d_out, int out_size)
{
    const float* x      = (const float*)d_in[0];   // [64,236,768]
    const float* qkv_w  = (const float*)d_in[1];   // [2304,768]
    const float* proj_w = (const float*)d_in[2];   // [768,768]
    const float* proj_b = (const float*)d_in[3];   // [768]
    float* out = (float*)d_out;                    // [64,236,768]

    __half *qkvh, *P, *vth, *atth, *xh, *wh, *pwh;
    float *S;
    cudaGetSymbolAddress((void**)&qkvh, g_qkvh);
    cudaGetSymbolAddress((void**)&S,    g_S);
    cudaGetSymbolAddress((void**)&P,    g_P);
    cudaGetSymbolAddress((void**)&vth,  g_vth);
    cudaGetSymbolAddress((void**)&atth, g_atth);
    cudaGetSymbolAddress((void**)&xh,   g_xh);
    cudaGetSymbolAddress((void**)&wh,   g_wh);
    cudaGetSymbolAddress((void**)&pwh,  g_pwh);

    const int SMEM = 40960;   // 2 stages x 20480 B
    const float scale = 0.10206207261596575f;      // 1/sqrt(96)

    // 0) convert inputs to fp16
    cvt_h<<<(15104 * 768 / 4 + 255) / 256, 256>>>(x, xh, 15104 * 768 / 4);
    cvt_h<<<(2304 * 768 / 4 + 255) / 256, 256>>>(qkv_w, wh, 2304 * 768 / 4);
    cvt_h<<<(768 * 768 / 4 + 255) / 256, 256>>>(proj_w, pwh, 768 * 768 / 4);

    // 1) qkvh = x @ qkv_w^T            [15104 x 2304], K=768, fp16 out
    hgemm<true, false><<<dim3(118, 18, 1), 256, SMEM>>>(
        xh, wh, nullptr, qkvh,
        15104, 2304, 768, 768, 768, 2304,
        1, 0, 0, 0, 0, 0, 0, 1.0f);

    // 2) S[bh] = (Q @ K^T) * scale     512 batches, 236x236, K=96, fp32 out
    hgemm<false, false><<<dim3(2, 2, 512), 256, SMEM>>>(
        qkvh, qkvh + 768, nullptr, S,
        236, 236, 96, 2304, 2304, 236,
        8, (long)236 * 2304, 96, (long)236 * 2304, 96,
        (long)8 * 236 * 236, (long)236 * 236,
        scale);

    // 3) block edits + softmax: S fp32 -> P fp16 (padded to 240)
    softmax_edit_kernel<<<dim3(236, 512), 256>>>(S, P);

    // 3b) V transpose -> vth fp16 (padded to 240)
    vtrans_kernel<<<dim3(8, 3, 512), dim3(32, 8)>>>(qkvh, vth);

    // 4) atth[bh] = P @ vth^T          512 batches, 236x96, K=240(padded), fp16 out
    //    P batch stride 236*240 per bh (= 8*236*240 per b, 236*240 per h);
    //    vth likewise. FIXED from R9: per-head strides were dropped.
    hgemm<true, false><<<dim3(2, 1, 512), 256, SMEM>>>(
        P, vth, nullptr, atth,
        236, 96, 240, 240, 240, 768,
        8, (long)8 * 236 * 240, (long)236 * 240,
        (long)8 * 96 * 240, (long)96 * 240,
        (long)236 * 768, 96,
        1.0f);

    // 5) out = atth @ proj_w^T + proj_b  [15104 x 768], K=768, fp32 out + bias
    hgemm<false, true><<<dim3(118, 6, 1), 256, SMEM>>>(
        atth, pwh, proj_b, out,
        15104, 768, 768, 768, 768, 768,
        1, 0, 0, 0, 0, 0, 0, 1.0f);
}

// round 12
// speedup vs baseline: 4.5001x; 1.0330x over previous
#include <cuda_runtime.h>
#include <cuda_fp16.h>
#include <cstdint>
#include <math.h>

// ---------------------------------------------------------------------------
// Problem: B=64, N=236, C=768, H=8, D=96.  M = B*N = 15104 = 118*128.
// Scratch (static device globals -- no runtime allocation allowed)
// ---------------------------------------------------------------------------
__device__ __half g_qkvh[(size_t)15104 * 2304];  // [B*N, 3C] fp16
__device__ float  g_S[(size_t)512 * 236 * 236];  // [B*H, 236, 236] fp32 logits
__device__ __half g_P[(size_t)512 * 236 * 240];  // probs fp16, K-padded to 240
__device__ __half g_vth[(size_t)512 * 96 * 240]; // V^T fp16, padded to 240
__device__ __half g_atth[(size_t)15104 * 768];   // attention out fp16
__device__ __half g_xh[(size_t)15104 * 768];     // x fp16
__device__ __half g_wh[(size_t)2304 * 768];      // qkv_w fp16
__device__ __half g_pwh[(size_t)768 * 768];      // proj_w fp16

// ---------------------------------------------------------------------------
__device__ __forceinline__ uint32_t smem_u32(const void* p) {
    uint32_t a;
    asm("{ .reg .u64 t; cvta.to.shared.u64 t, %1; cvt.u32.u64 %0, t; }" : "=r"(a) : "l"(p));
    return a;
}
__device__ __forceinline__ void mma_f16(float* c, const uint32_t* a, const uint32_t* b) {
    asm volatile(
        "mma.sync.aligned.m16n8k16.row.col.f32.f16.f16.f32 "
        "{%0,%1,%2,%3}, {%4,%5,%6,%7}, {%8,%9}, {%0,%1,%2,%3};"
        : "+f"(c[0]), "+f"(c[1]), "+f"(c[2]), "+f"(c[3])
        : "r"(a[0]), "r"(a[1]), "r"(a[2]), "r"(a[3]), "r"(b[0]), "r"(b[1]));
}
#define LDMX4(r, addr) \
    asm volatile("ldmatrix.sync.aligned.m8n8.x4.shared.b16 {%0,%1,%2,%3}, [%4];" \
                 : "=r"((r)[0]), "=r"((r)[1]), "=r"((r)[2]), "=r"((r)[3]) : "r"(addr))
// cp.async 16B; when !pred copies 0 source bytes -> dst 16B zero-filled
__device__ __forceinline__ void cpa16(uint32_t dst, const void* src, bool pred) {
    int sz = pred ? 16 : 0;
    asm volatile("cp.async.cg.shared.global [%0], [%1], 16, %2;"
                 :: "r"(dst), "l"(src), "r"(sz) : "memory");
}

// ---------------------------------------------------------------------------
// fp16 tensor-core batched NT GEMM: C[m,n] = alpha*sum_k A[m,k]*B[n,k] (+bias[n])
// A,B fp16; accumulate fp32; C fp32 or fp16 (OUT_HALF).
// 128x128x32 tile, 256 threads, 8 warps (4x2), warp tile 32x64,
// 4-stage cp.async pipeline with ONE __syncthreads per k-tile,
// ldmatrix fragment loads.
// smem per stage per operand: 128 rows x 40 halves (80B pitch) = 10240 B.
// Stage stride 20480 B; 4 stages = 81920 B.
// ---------------------------------------------------------------------------
template<bool OUT_HALF, bool ADD_BIAS>
__global__ void __launch_bounds__(256, 2)
hgemm(const __half* __restrict__ Ag, const __half* __restrict__ Bg,
      const float* __restrict__ bias, void* __restrict__ Cv,
      int M, int N, int K, int lda, int ldb, int ldc,
      int HB, long sAb, long sAh, long sBb, long sBh, long sCb, long sCh,
      float alpha)
{
    extern __shared__ __half smem[];   // 40960 halves = 81920 B

    const int z  = blockIdx.z;
    const int hb = z % HB, bb = z / HB;
    const __half* A = Ag + (size_t)bb * sAb + (size_t)hb * sAh;
    const __half* B = Bg + (size_t)bb * sBb + (size_t)hb * sBh;

    const int bm = blockIdx.x * 128, bn = blockIdx.y * 128;
    const int tid = threadIdx.x, lane = tid & 31, wid = tid >> 5;
    const int wr = wid & 3, wc = wid >> 2;     // warp row (x32), warp col (x64)
    const int q = lane >> 2, r = lane & 3;
    const uint32_t sbase = smem_u32(smem);

    // ldmatrix lane address components
    const int lt = lane >> 3, li = lane & 7;
    const int aRow = wr * 32 + (lt & 1) * 8 + li;    // + t2*16
    const int aCol = (lt >> 1) * 16;                  // bytes; + ks*2
    const int bRow = wc * 64 + (lt >> 1) * 8 + li;    // + jp*16
    const int bCol = (lt & 1) * 16;                   // bytes; + ks*2

    float acc[2][8][4];
#pragma unroll
    for (int t2 = 0; t2 < 2; t2++)
#pragma unroll
        for (int j = 0; j < 8; j++)
#pragma unroll
            for (int u = 0; u < 4; u++) acc[t2][j][u] = 0.0f;

    // one BK=32 tile per operand: 128 rows x 4 chunks(8 halves) = 512 chunks
    auto issue = [&](int stage, int t) {
        const int k0 = t * 32;
#pragma unroll
        for (int i = 0; i < 2; i++) {   // A
            int cid = tid + i * 256;
            int m = cid >> 2, c8 = cid & 3;
            int gc = k0 + c8 * 8;
            int gr = bm + m;
            bool p = (gr < M) && (gc + 8 <= K);
            const __half* src = p ? (A + (size_t)gr * lda + gc) : A;
            cpa16(sbase + (uint32_t)(stage * 20480 + m * 80 + c8 * 16), src, p);
        }
#pragma unroll
        for (int i = 0; i < 2; i++) {   // B
            int cid = tid + i * 256;
            int m = cid >> 2, c8 = cid & 3;
            int gc = k0 + c8 * 8;
            int gr = bn + m;
            bool p = (gr < N) && (gc + 8 <= K);
            const __half* src = p ? (B + (size_t)gr * ldb + gc) : B;
            cpa16(sbase + (uint32_t)(stage * 20480 + 10240 + m * 80 + c8 * 16), src, p);
        }
    };

    auto compute = [&](int stage) {
        const uint32_t baseA = sbase + stage * 20480;
        const uint32_t baseB = baseA + 10240;
#pragma unroll
        for (int ks = 0; ks < 32; ks += 16) {
            uint32_t a[2][4], b[4][4];
#pragma unroll
            for (int t2 = 0; t2 < 2; t2++)
                LDMX4(a[t2], baseA + (uint32_t)((aRow + t2 * 16) * 80 + aCol + ks * 2));
#pragma unroll
            for (int jp = 0; jp < 4; jp++)
                LDMX4(b[jp], baseB + (uint32_t)((bRow + jp * 16) * 80 + bCol + ks * 2));
#pragma unroll
            for (int t2 = 0; t2 < 2; t2++)
#pragma unroll
                for (int j = 0; j < 8; j++) {
                    uint32_t bb2[2] = { b[j >> 1][(j & 1) * 2], b[j >> 1][(j & 1) * 2 + 1] };
                    mma_f16(acc[t2][j], a[t2], bb2);
                }
        }
    };

    const int ntiles = (K + 31) / 32;

    // prologue: fill 3 of 4 stages
#pragma unroll
    for (int p = 0; p < 3; p++) {
        if (p < ntiles) issue(p, p);
        asm volatile("cp.async.commit_group;" ::: "memory");
    }

    for (int t = 0; t < ntiles; t++) {
        // groups committed so far: t+3. wait_group 2 -> all but last 2 done,
        // so tile t's group is complete.
        asm volatile("cp.async.wait_group 2;" ::: "memory");
        __syncthreads();
        // refill stage (t+3)&3: last read by compute(t-1), which finished
        // before the sync above.
        if (t + 3 < ntiles) issue((t + 3) & 3, t + 3);
        asm volatile("cp.async.commit_group;" ::: "memory");
        compute(t & 3);
    }

    // epilogue: c0,c1 -> (row, col..col+1), c2,c3 -> (row+8, ...)
#pragma unroll
    for (int t2 = 0; t2 < 2; t2++) {
#pragma unroll
        for (int j = 0; j < 8; j++) {
            int col = bn + wc * 64 + j * 8 + r * 2;
            if (col >= N) continue;
            int row0 = bm + wr * 32 + t2 * 16 + q;
            float bx = 0.f, by = 0.f;
            if (ADD_BIAS) { bx = bias[col]; by = bias[col + 1]; }
#pragma unroll
            for (int h = 0; h < 2; h++) {
                int row = row0 + h * 8;
                if (row >= M) continue;
                float vx = acc[t2][j][h * 2 + 0] * alpha + bx;
                float vy = acc[t2][j][h * 2 + 1] * alpha + by;
                if (OUT_HALF) {
                    __half2* dst = reinterpret_cast<__half2*>(
                        (__half*)Cv + (size_t)bb * sCb + (size_t)hb * sCh + (size_t)row * ldc + col);
                    *dst = __floats2half2_rn(vx, vy);
                } else {
                    float2* dst = reinterpret_cast<float2*>(
                        (float*)Cv + (size_t)bb * sCb + (size_t)hb * sCh + (size_t)row * ldc + col);
                    *dst = make_float2(vx, vy);
                }
            }
        }
    }
}

// ---------------------------------------------------------------------------
// fp32 -> fp16 conversion (4 floats / thread)
// ---------------------------------------------------------------------------
__global__ void cvt_h(const float* __restrict__ in, __half* __restrict__ out, int n4)
{
    int i = blockIdx.x * blockDim.x + threadIdx.x;
    if (i < n4) {
        float4 v = reinterpret_cast<const float4*>(in)[i];
        uint2 u;
        __half2 h0 = __floats2half2_rn(v.x, v.y);
        __half2 h1 = __floats2half2_rn(v.z, v.w);
        u.x = *reinterpret_cast<uint32_t*>(&h0);
        u.y = *reinterpret_cast<uint32_t*>(&h1);
        reinterpret_cast<uint2*>(out)[i] = u;
    }
}

// ---------------------------------------------------------------------------
// V transpose fp16: vth[bh][d][tok] = qkvh[(b*236+tok)*2304 + 1536 + h*96 + d]
// Output pitch 240 (tok 236..239 zero-filled).
// ---------------------------------------------------------------------------
__global__ void vtrans_kernel(const __half* __restrict__ qkvh, __half* __restrict__ vt)
{
    __shared__ float t[32][33];
    const int bh = blockIdx.z;
    const int b = bh >> 3, h = bh & 7;
    const int t0 = blockIdx.x * 32;
    const int d0 = blockIdx.y * 32;
    const int tx = threadIdx.x, ty = threadIdx.y;

#pragma unroll
    for (int r = ty; r < 32; r += 8) {
        int tok = t0 + r;
        int d = d0 + tx;
        float v = 0.f;
        if (tok < 236)
            v = __half2float(qkvh[(size_t)(b * 236 + tok) * 2304 + 1536 + h * 96 + d]);
        t[r][tx] = v;
    }
    __syncthreads();
#pragma unroll
    for (int r = ty; r < 32; r += 8) {
        int d = d0 + r;
        int tok = t0 + tx;
        if (tok < 240)
            vt[((size_t)bh * 96 + d) * 240 + tok] =
                (tok < 236) ? __float2half_rn(t[tx][r]) : __float2half_rn(0.f);
    }
}

// ---------------------------------------------------------------------------
// Block edits + softmax. Reads fp32 logits S[bh][236][236], writes fp16
// probabilities P[bh][236][240] (cols 236..239 zeroed).
// ---------------------------------------------------------------------------
__global__ void softmax_edit_kernel(const float* __restrict__ S, __half* __restrict__ P)
{
    const int r  = blockIdx.x;   // 0..235
    const int bh = blockIdx.y;   // 0..511
    const float* srow = S + ((size_t)bh * 236 + r) * 236;
    __half* prow = P + ((size_t)bh * 236 + r) * 240;
    const int c = threadIdx.x;

    float v = -1e30f;
    if (c < 236) {
        float s;
        if (r < 196) {
            if (c >= 216)      s = srow[c - 20];      // copy uses PRE-bias values
            else if (c >= 196) s = srow[c] - 100.0f;
            else               s = srow[c];
        } else if (r < 216) {
            s = srow[c] - ((c >= 216) ? 100.0f : 0.0f);
        } else {
            s = srow[c] - ((c >= 196 && c < 216) ? 100.0f : 0.0f);
        }
        v = s;
    }

    __shared__ float red[8];
    float m = v;
#pragma unroll
    for (int o = 16; o > 0; o >>= 1) m = fmaxf(m, __shfl_xor_sync(0xffffffffu, m, o));
    if ((c & 31) == 0) red[c >> 5] = m;
    __syncthreads();
    float mx = fmaxf(fmaxf(fmaxf(red[0], red[1]), fmaxf(red[2], red[3])),
                     fmaxf(fmaxf(red[4], red[5]), fmaxf(red[6], red[7])));

    float e = (c < 236) ? expf(v - mx) : 0.0f;
    float ssum = e;
#pragma unroll
    for (int o = 16; o > 0; o >>= 1) ssum += __shfl_xor_sync(0xffffffffu, ssum, o);
    __syncthreads();
    if ((c & 31) == 0) red[c >> 5] = ssum;
    __syncthreads();
    float tot = red[0] + red[1] + red[2] + red[3] + red[4] + red[5] + red[6] + red[7];

    if (c < 240) prow[c] = (c < 236) ? __float2half_rn(e / tot) : __float2half_rn(0.f);
}

// ---------------------------------------------------------------------------
extern "C" void kernel_launch(void* const* d_in, const int* in_sizes, int n_in,
                              void* d_out, int out_size)
{
    const float* x      = (const float*)d_in[0];   // [64,236,768]
    const float* qkv_w  = (const float*)d_in[1];   // [2304,768]
    const float* proj_w = (const float*)d_in[2];   // [768,768]
    const float* proj_b = (const float*)d_in[3];   // [768]
    float* out = (float*)d_out;                    // [64,236,768]

    __half *qkvh, *P, *vth, *atth, *xh, *wh, *pwh;
    float *S;
    cudaGetSymbolAddress((void**)&qkvh, g_qkvh);
    cudaGetSymbolAddress((void**)&S,    g_S);
    cudaGetSymbolAddress((void**)&P,    g_P);
    cudaGetSymbolAddress((void**)&vth,  g_vth);
    cudaGetSymbolAddress((void**)&atth, g_atth);
    cudaGetSymbolAddress((void**)&xh,   g_xh);
    cudaGetSymbolAddress((void**)&wh,   g_wh);
    cudaGetSymbolAddress((void**)&pwh,  g_pwh);

    const int SMEM = 81920;   // 4 stages x 20480 B
    cudaFuncSetAttribute(hgemm<true,  false>, cudaFuncAttributeMaxDynamicSharedMemorySize, SMEM);
    cudaFuncSetAttribute(hgemm<false, false>, cudaFuncAttributeMaxDynamicSharedMemorySize, SMEM);
    cudaFuncSetAttribute(hgemm<false, true>,  cudaFuncAttributeMaxDynamicSharedMemorySize, SMEM);

    const float scale = 0.10206207261596575f;      // 1/sqrt(96)

    // 0) convert inputs to fp16
    cvt_h<<<(15104 * 768 / 4 + 255) / 256, 256>>>(x, xh, 15104 * 768 / 4);
    cvt_h<<<(2304 * 768 / 4 + 255) / 256, 256>>>(qkv_w, wh, 2304 * 768 / 4);
    cvt_h<<<(768 * 768 / 4 + 255) / 256, 256>>>(proj_w, pwh, 768 * 768 / 4);

    // 1) qkvh = x @ qkv_w^T            [15104 x 2304], K=768, fp16 out
    hgemm<true, false><<<dim3(118, 18, 1), 256, SMEM>>>(
        xh, wh, nullptr, qkvh,
        15104, 2304, 768, 768, 768, 2304,
        1, 0, 0, 0, 0, 0, 0, 1.0f);

    // 2) S[bh] = (Q @ K^T) * scale     512 batches, 236x236, K=96, fp32 out
    hgemm<false, false><<<dim3(2, 2, 512), 256, SMEM>>>(
        qkvh, qkvh + 768, nullptr, S,
        236, 236, 96, 2304, 2304, 236,
        8, (long)236 * 2304, 96, (long)236 * 2304, 96,
        (long)8 * 236 * 236, (long)236 * 236,
        scale);

    // 3) block edits + softmax: S fp32 -> P fp16 (padded to 240)
    softmax_edit_kernel<<<dim3(236, 512), 256>>>(S, P);

    // 3b) V transpose -> vth fp16 (padded to 240)
    vtrans_kernel<<<dim3(8, 3, 512), dim3(32, 8)>>>(qkvh, vth);

    // 4) atth[bh] = P @ vth^T          512 batches, 236x96, K=240(padded), fp16 out
    hgemm<true, false><<<dim3(2, 1, 512), 256, SMEM>>>(
        P, vth, nullptr, atth,
        236, 96, 240, 240, 240, 768,
        8, (long)8 * 236 * 240, (long)236 * 240,
        (long)8 * 96 * 240, (long)96 * 240,
        (long)236 * 768, 96,
        1.0f);

    // 5) out = atth @ proj_w^T + proj_b  [15104 x 768], K=768, fp32 out + bias
    hgemm<false, true><<<dim3(118, 6, 1), 256, SMEM>>>(
        atth, pwh, proj_b, out,
        15104, 768, 768, 768, 768, 768,
        1, 0, 0, 0, 0, 0, 0, 1.0f);
}